// round 1
// baseline (speedup 1.0000x reference)
#include <cuda_runtime.h>
#include <cuda_bf16.h>
#include <cstdint>

// ForMicroLoss: loss = sum_{t==1} softplus(-p)/n_pos + sum_{t==0} softplus(p)/n_neg
// N*K = 8192*8192 = 64M elements. HBM-bound reduction (512 MB read).

#define GRID1 2368   // 148 SMs * 16 blocks
#define BLOCK1 256
#define BLOCK2 1024

// Per-block partials (no dynamic allocation allowed).
__device__ float g_pos[GRID1];
__device__ float g_neg[GRID1];
__device__ int   g_np[GRID1];
__device__ int   g_nn[GRID1];

__device__ __forceinline__ float softplus_fast(float p) {
    // softplus(p) = max(p,0) + log(1 + exp(-|p|)); fast-math MUFU version.
    float e = __expf(-fabsf(p));
    return fmaxf(p, 0.0f) + __logf(1.0f + e);
}

__device__ __forceinline__ void accum_one(float p, int t,
                                          float& pos, float& neg,
                                          int& np, int& nn) {
    float sp = softplus_fast(p);
    if (t == 1) { pos += sp - p; np++; }   // softplus(-p) = softplus(p) - p
    if (t == 0) { neg += sp;     nn++; }
}

__global__ __launch_bounds__(BLOCK1)
void fml_partial_kernel(const float4* __restrict__ pred4,
                        const int4*  __restrict__ true4,
                        int n4, const float* __restrict__ pred,
                        const int* __restrict__ truth, int n) {
    float pos = 0.0f, neg = 0.0f;
    int np = 0, nn = 0;

    const int stride = gridDim.x * blockDim.x;
    int i = blockIdx.x * blockDim.x + threadIdx.x;

    for (; i < n4; i += stride) {
        float4 p = pred4[i];
        int4   t = true4[i];
        accum_one(p.x, t.x, pos, neg, np, nn);
        accum_one(p.y, t.y, pos, neg, np, nn);
        accum_one(p.z, t.z, pos, neg, np, nn);
        accum_one(p.w, t.w, pos, neg, np, nn);
    }

    // Scalar tail (n not divisible by 4 — not the case here, but safe).
    int tail_start = n4 * 4;
    int gtid = blockIdx.x * blockDim.x + threadIdx.x;
    for (int j = tail_start + gtid; j < n; j += stride) {
        accum_one(pred[j], truth[j], pos, neg, np, nn);
    }

    // Warp reduction.
    #pragma unroll
    for (int off = 16; off > 0; off >>= 1) {
        pos += __shfl_down_sync(0xffffffffu, pos, off);
        neg += __shfl_down_sync(0xffffffffu, neg, off);
        np  += __shfl_down_sync(0xffffffffu, np,  off);
        nn  += __shfl_down_sync(0xffffffffu, nn,  off);
    }

    __shared__ float s_pos[BLOCK1 / 32];
    __shared__ float s_neg[BLOCK1 / 32];
    __shared__ int   s_np[BLOCK1 / 32];
    __shared__ int   s_nn[BLOCK1 / 32];

    int wid  = threadIdx.x >> 5;
    int lane = threadIdx.x & 31;
    if (lane == 0) {
        s_pos[wid] = pos; s_neg[wid] = neg;
        s_np[wid]  = np;  s_nn[wid]  = nn;
    }
    __syncthreads();

    if (threadIdx.x == 0) {
        float bp = 0.0f, bn = 0.0f;
        int bnp = 0, bnn = 0;
        #pragma unroll
        for (int w = 0; w < BLOCK1 / 32; w++) {
            bp  += s_pos[w]; bn  += s_neg[w];
            bnp += s_np[w];  bnn += s_nn[w];
        }
        g_pos[blockIdx.x] = bp;
        g_neg[blockIdx.x] = bn;
        g_np[blockIdx.x]  = bnp;
        g_nn[blockIdx.x]  = bnn;
    }
}

__global__ __launch_bounds__(BLOCK2)
void fml_final_kernel(float* __restrict__ out) {
    double pos = 0.0, neg = 0.0;
    long long np = 0, nn = 0;

    for (int i = threadIdx.x; i < GRID1; i += BLOCK2) {
        pos += (double)g_pos[i];
        neg += (double)g_neg[i];
        np  += (long long)g_np[i];
        nn  += (long long)g_nn[i];
    }

    __shared__ double sh_pos[BLOCK2];
    __shared__ double sh_neg[BLOCK2];
    __shared__ long long sh_np[BLOCK2];
    __shared__ long long sh_nn[BLOCK2];

    sh_pos[threadIdx.x] = pos;
    sh_neg[threadIdx.x] = neg;
    sh_np[threadIdx.x]  = np;
    sh_nn[threadIdx.x]  = nn;
    __syncthreads();

    // Deterministic tree reduction.
    for (int s = BLOCK2 / 2; s > 0; s >>= 1) {
        if (threadIdx.x < s) {
            sh_pos[threadIdx.x] += sh_pos[threadIdx.x + s];
            sh_neg[threadIdx.x] += sh_neg[threadIdx.x + s];
            sh_np[threadIdx.x]  += sh_np[threadIdx.x + s];
            sh_nn[threadIdx.x]  += sh_nn[threadIdx.x + s];
        }
        __syncthreads();
    }

    if (threadIdx.x == 0) {
        double np_d = (double)sh_np[0];
        double nn_d = (double)sh_nn[0];
        double result = sh_pos[0] / np_d + sh_neg[0] / nn_d;
        out[0] = (float)result;
    }
}

extern "C" void kernel_launch(void* const* d_in, const int* in_sizes, int n_in,
                              void* d_out, int out_size) {
    const float* pred = (const float*)d_in[0];
    const int*   truth = (const int*)d_in[1];
    float* out = (float*)d_out;

    int n  = in_sizes[0];
    int n4 = n >> 2;

    fml_partial_kernel<<<GRID1, BLOCK1>>>(
        (const float4*)pred, (const int4*)truth, n4, pred, truth, n);
    fml_final_kernel<<<1, BLOCK2>>>(out);
}

// round 2
// speedup vs baseline: 1.1718x; 1.1718x over previous
#include <cuda_runtime.h>
#include <cuda_bf16.h>
#include <cstdint>

// ForMicroLoss: loss = sum_{t==1} softplus(-p)/n_pos + sum_{t==0} softplus(p)/n_neg
// 64M elements, 512 MB read -> HBM-bound. Single persistent-style kernel with
// last-block-done final reduction (deterministic: fixed-order double sum).

#define GRID1  1184    // 148 SMs * 8
#define BLOCK1 512

__device__ float g_pos[GRID1];
__device__ float g_neg[GRID1];
__device__ int   g_np[GRID1];
__device__ unsigned int g_count;   // zero-initialized; reset after each use

__device__ __forceinline__ float softplus_fast(float p) {
    // softplus(p) = max(p,0) + log(1 + exp(-|p|))
    float e = __expf(-fabsf(p));
    return fmaxf(p, 0.0f) + __logf(1.0f + e);
}

// Branchless: t in {0,1}.
// pos-term contribution: t * (softplus(p) - p)   [= softplus(-p) when t==1]
// neg-term contribution: (1-t) * softplus(p)
__device__ __forceinline__ void accum_one(float p, int t,
                                          float& pos, float& neg, int& np) {
    float sp = softplus_fast(p);
    float ft = (float)t;
    pos = fmaf(ft, sp - p, pos);
    neg = fmaf(1.0f - ft, sp, neg);
    np += t;
}

__global__ __launch_bounds__(BLOCK1)
void fml_kernel(const float4* __restrict__ pred4,
                const int4*  __restrict__ true4,
                int n4,
                const float* __restrict__ pred,
                const int* __restrict__ truth,
                int n,
                float* __restrict__ out) {
    float pos = 0.0f, neg = 0.0f;
    int np = 0;

    const int stride = gridDim.x * blockDim.x;
    const int tid0 = blockIdx.x * blockDim.x + threadIdx.x;

    // Unroll x2 over grid-stride: 4 independent 16B loads front-batched.
    int i = tid0;
    for (; i + stride < n4; i += 2 * stride) {
        float4 p0 = __ldcs(&pred4[i]);
        float4 p1 = __ldcs(&pred4[i + stride]);
        int4   t0 = __ldcs(&true4[i]);
        int4   t1 = __ldcs(&true4[i + stride]);
        accum_one(p0.x, t0.x, pos, neg, np);
        accum_one(p0.y, t0.y, pos, neg, np);
        accum_one(p0.z, t0.z, pos, neg, np);
        accum_one(p0.w, t0.w, pos, neg, np);
        accum_one(p1.x, t1.x, pos, neg, np);
        accum_one(p1.y, t1.y, pos, neg, np);
        accum_one(p1.z, t1.z, pos, neg, np);
        accum_one(p1.w, t1.w, pos, neg, np);
    }
    if (i < n4) {
        float4 p0 = __ldcs(&pred4[i]);
        int4   t0 = __ldcs(&true4[i]);
        accum_one(p0.x, t0.x, pos, neg, np);
        accum_one(p0.y, t0.y, pos, neg, np);
        accum_one(p0.z, t0.z, pos, neg, np);
        accum_one(p0.w, t0.w, pos, neg, np);
    }

    // Scalar tail (n % 4 != 0 — not hit for 64M, kept for safety).
    for (int j = n4 * 4 + tid0; j < n; j += stride) {
        accum_one(pred[j], truth[j], pos, neg, np);
    }

    // Warp reduction.
    #pragma unroll
    for (int off = 16; off > 0; off >>= 1) {
        pos += __shfl_down_sync(0xffffffffu, pos, off);
        neg += __shfl_down_sync(0xffffffffu, neg, off);
        np  += __shfl_down_sync(0xffffffffu, np,  off);
    }

    __shared__ float s_pos[BLOCK1 / 32];
    __shared__ float s_neg[BLOCK1 / 32];
    __shared__ int   s_np[BLOCK1 / 32];

    int wid  = threadIdx.x >> 5;
    int lane = threadIdx.x & 31;
    if (lane == 0) { s_pos[wid] = pos; s_neg[wid] = neg; s_np[wid] = np; }
    __syncthreads();

    __shared__ bool s_last;
    if (threadIdx.x == 0) {
        float bp = 0.0f, bn = 0.0f; int bnp = 0;
        #pragma unroll
        for (int w = 0; w < BLOCK1 / 32; w++) {
            bp += s_pos[w]; bn += s_neg[w]; bnp += s_np[w];
        }
        g_pos[blockIdx.x] = bp;
        g_neg[blockIdx.x] = bn;
        g_np[blockIdx.x]  = bnp;
        __threadfence();
        unsigned int done = atomicAdd(&g_count, 1u);
        s_last = (done == (unsigned)(gridDim.x - 1));
    }
    __syncthreads();

    if (!s_last) return;

    // ---- Last block: deterministic fixed-order final reduction ----
    double dpos = 0.0, dneg = 0.0;
    long long dnp = 0;
    for (int k = threadIdx.x; k < GRID1; k += BLOCK1) {
        dpos += (double)g_pos[k];
        dneg += (double)g_neg[k];
        dnp  += (long long)g_np[k];
    }

    __shared__ double sh_pos[BLOCK1];
    __shared__ double sh_neg[BLOCK1];
    __shared__ long long sh_np[BLOCK1];
    sh_pos[threadIdx.x] = dpos;
    sh_neg[threadIdx.x] = dneg;
    sh_np[threadIdx.x]  = dnp;
    __syncthreads();

    for (int s = BLOCK1 / 2; s > 0; s >>= 1) {
        if (threadIdx.x < s) {
            sh_pos[threadIdx.x] += sh_pos[threadIdx.x + s];
            sh_neg[threadIdx.x] += sh_neg[threadIdx.x + s];
            sh_np[threadIdx.x]  += sh_np[threadIdx.x + s];
        }
        __syncthreads();
    }

    if (threadIdx.x == 0) {
        double np_d = (double)sh_np[0];
        double nn_d = (double)n - np_d;
        out[0] = (float)(sh_pos[0] / np_d + sh_neg[0] / nn_d);
        g_count = 0;   // reset for next graph replay (deterministic)
    }
}

extern "C" void kernel_launch(void* const* d_in, const int* in_sizes, int n_in,
                              void* d_out, int out_size) {
    const float* pred  = (const float*)d_in[0];
    const int*   truth = (const int*)d_in[1];
    float* out = (float*)d_out;

    int n  = in_sizes[0];
    int n4 = n >> 2;

    fml_kernel<<<GRID1, BLOCK1>>>(
        (const float4*)pred, (const int4*)truth, n4, pred, truth, n, out);
}